// round 6
// baseline (speedup 1.0000x reference)
#include <cuda_runtime.h>

#define NN      25200
#define KSEL    2048
#define NCLS    80
#define CONF_T  0.4f
#define IOU_T   0.45f
#define MAXDET  1000
#define MAXWH   7680.0f
#define ROWW    32          /* 2048/64 uint64 words per mask row */
#define IMG_PIX (640*640)

/* ---------------- scratch (device globals; no allocation) ---------------- */
__device__ float              g_scores[NN];
__device__ float              g_cls[NN];
__device__ unsigned           g_key32[NN];
__device__ float              g_topS[KSEL];
__device__ float4             g_b[KSEL];      /* unshifted xyxy of sorted cands */
__device__ float              g_c[KSEL];      /* class as float */
__device__ float4             g_boff[KSEL];   /* class-offset boxes for IoU */
__device__ unsigned long long g_maskM[KSEL * ROWW]; /* suppression bitmatrix */

/* ---------------- stage 1: per-anchor conf / cls / sortable key ---------- */
__global__ void prep_kernel(const float* __restrict__ pred) {
    int anchor = (blockIdx.x * blockDim.x + threadIdx.x) >> 5;
    int lane   = threadIdx.x & 31;
    if (anchor >= NN) return;
    const float* row = pred + (long long)anchor * 85;
    float obj = row[4];
    float best = -1.0f;
    int   bc   = 0;
    for (int j = lane; j < NCLS; j += 32) {
        float v = __fmul_rn(row[5 + j], obj);
        if (v > best) { best = v; bc = j; }       /* strict > -> first max */
    }
    /* warp argmax, ties -> lowest class index (jnp.argmax semantics) */
    for (int off = 16; off; off >>= 1) {
        float ov = __shfl_down_sync(0xffffffffu, best, off);
        int   oc = __shfl_down_sync(0xffffffffu, bc, off);
        if (ov > best || (ov == best && oc < bc)) { best = ov; bc = oc; }
    }
    if (lane == 0) {
        float s = (best > CONF_T) ? best : -1.0f;
        g_scores[anchor] = s;
        g_cls[anchor]    = (float)bc;
        unsigned u = __float_as_uint(s);
        g_key32[anchor] = (u >> 31) ? ~u : (u | 0x80000000u);  /* order-preserving */
    }
}

/* -------- stage 2: radix-select + bitonic top-2048 + fused gather -------- */
__global__ void topk_kernel(const float* __restrict__ pred) {
    __shared__ int bins[256];
    __shared__ int s_sel, s_acc, s_cnt;
    __shared__ unsigned long long key64[KSEL];
    int tid = threadIdx.x;

    /* 4x8-bit radix select: find T = 2048th-largest key */
    unsigned prefixv = 0;
    int need = KSEL;
    for (int shift = 24; shift >= 0; shift -= 8) {
        for (int b = tid; b < 256; b += blockDim.x) bins[b] = 0;
        __syncthreads();
        unsigned hmask = (shift == 24) ? 0u : (0xFFFFFFFFu << (shift + 8));
        for (int i = tid; i < NN; i += blockDim.x) {
            unsigned k = g_key32[i];
            if ((k & hmask) == prefixv) atomicAdd(&bins[(k >> shift) & 255], 1);
        }
        __syncthreads();
        if (tid == 0) {
            int acc = 0, v = 0;
            for (int b = 255; b >= 0; b--) {
                if (acc + bins[b] >= need) { v = b; break; }
                acc += bins[b];
            }
            s_sel = v; s_acc = acc;
        }
        __syncthreads();
        prefixv |= ((unsigned)s_sel) << shift;
        need -= s_acc;
        __syncthreads();
    }

    /* gather all keys >= T (>= 2048 exist), cap at 2048 */
    if (tid == 0) s_cnt = 0;
    __syncthreads();
    for (int i = tid; i < NN; i += blockDim.x) {
        unsigned k = g_key32[i];
        if (k >= prefixv) {
            int p = atomicAdd(&s_cnt, 1);
            if (p < KSEL)
                key64[p] = (((unsigned long long)k) << 32) | (unsigned)(~(unsigned)i);
        }
    }
    __syncthreads();

    /* bitonic sort 2048 keys descending; ~index low bits => lowest index
       wins ties; gather order becomes irrelevant (deterministic) */
    for (unsigned k = 2; k <= KSEL; k <<= 1) {
        for (unsigned j = k >> 1; j; j >>= 1) {
            for (unsigned t = tid; t < KSEL; t += blockDim.x) {
                unsigned l = t ^ j;
                if (l > t) {
                    unsigned long long a = key64[t], b = key64[l];
                    bool descBlk = ((t & k) == 0);
                    bool sw = descBlk ? (a < b) : (a > b);
                    if (sw) { key64[t] = b; key64[l] = a; }
                }
            }
            __syncthreads();
        }
    }

    /* fused gather: boxes, class offsets, scores */
    for (int t = tid; t < KSEL; t += blockDim.x) {
        unsigned long long kk = key64[t];
        int idx = (int)(~(unsigned)(kk & 0xFFFFFFFFull));
        g_topS[t] = g_scores[idx];
        const float* row = pred + (long long)idx * 85;
        float x = row[0], y = row[1], w = row[2], h = row[3];
        float hw = __fmul_rn(w, 0.5f), hh = __fmul_rn(h, 0.5f);
        float4 b;
        b.x = __fsub_rn(x, hw); b.y = __fsub_rn(y, hh);
        b.z = __fadd_rn(x, hw); b.w = __fadd_rn(y, hh);
        float c   = g_cls[idx];
        float off = __fmul_rn(c, MAXWH);
        float4 bo;
        bo.x = __fadd_rn(b.x, off); bo.y = __fadd_rn(b.y, off);
        bo.z = __fadd_rn(b.z, off); bo.w = __fadd_rn(b.w, off);
        g_b[t] = b; g_c[t] = c; g_boff[t] = bo;
    }
}

/* ------- stage 3: parallel 2048x2048 suppression bitmask (256 thr) ------- */
__global__ void mask_kernel() {
    __shared__ float4 jb[64];
    int jblk = blockIdx.x;
    int tid = threadIdx.x;
    if (tid < 64) jb[tid] = g_boff[jblk * 64 + tid];
    __syncthreads();
    int i = blockIdx.y * 256 + tid;
    float4 a = g_boff[i];
    float areaA = __fmul_rn(__fsub_rn(a.z, a.x), __fsub_rn(a.w, a.y));
    unsigned long long bits = 0;
    int jbase = jblk * 64;
    #pragma unroll 8
    for (int jj = 0; jj < 64; jj++) {
        int j = jbase + jj;
        if (j <= i) continue;                  /* ar > i */
        float4 bb = jb[jj];
        float lx = fmaxf(a.x, bb.x), ly = fmaxf(a.y, bb.y);
        float rx = fminf(a.z, bb.z), ry = fminf(a.w, bb.w);
        float w = fmaxf(__fsub_rn(rx, lx), 0.0f);
        float h = fmaxf(__fsub_rn(ry, ly), 0.0f);
        float inter = __fmul_rn(w, h);
        float areaB = __fmul_rn(__fsub_rn(bb.z, bb.x), __fsub_rn(bb.w, bb.y));
        float denom = __fadd_rn(__fsub_rn(__fadd_rn(areaA, areaB), inter), 1e-7f);
        float iou = __fdiv_rn(inter, denom);
        if (iou > IOU_T) bits |= (1ull << jj);
    }
    g_maskM[(long long)i * ROWW + jblk] = bits;
}

/* ------ stage 4: word-batched serial NMS (warp 0) + fused finalize ------- */
__global__ void nms_finalize_kernel(float* __restrict__ out) {
    __shared__ unsigned long long kw[ROWW];
    __shared__ int wpre[ROWW + 1];
    int tid = threadIdx.x;

    /* zero det output while warp 0 works */
    for (int e = tid; e < MAXDET * 6; e += blockDim.x) out[e] = 0.0f;

    if (tid < 32) {
        int lane = tid;                        /* lane owns bits [64l, 64l+64) */
        unsigned long long alive = 0;
        #pragma unroll 4
        for (int b = 0; b < 64; b++)
            if (g_topS[lane * 64 + b] > CONF_T) alive |= (1ull << b);

        for (int w = 0; w < ROWW; w++) {
            /* lane w: serial 64-step chain on the diagonal 64x64 block.
               Only this block affects alive-word w within its own i-range. */
            unsigned long long d = 0;
            if (lane == w) {
                const unsigned long long* diag = g_maskM + (size_t)(w * 64) * ROWW + w;
                #pragma unroll
                for (int b = 0; b < 64; b++) {
                    unsigned long long m =
                        (unsigned long long)((long long)(alive << (63 - b)) >> 63);
                    d |= m & (1ull << b);
                    alive &= ~(diag[(size_t)b * ROWW] & m);  /* LOP3 */
                }
            }
            /* broadcast decision word */
            unsigned lo = __shfl_sync(0xffffffffu, (unsigned)d, w);
            unsigned hi = __shfl_sync(0xffffffffu, (unsigned)(d >> 32), w);
            d = (((unsigned long long)hi) << 32) | lo;

            /* all lanes: OR the decided rows (64 independent loads, MLP),
               single and-not. Idempotent on the diagonal lane. */
            const unsigned long long* col = g_maskM + (size_t)(w * 64) * ROWW + lane;
            unsigned long long sup = 0;
            #pragma unroll
            for (int b = 0; b < 64; b++) {
                unsigned long long m =
                    (unsigned long long)((long long)(d << (63 - b)) >> 63);
                sup |= col[(size_t)b * ROWW] & m;
            }
            alive &= ~sup;
        }
        kw[lane] = alive;
    }
    __syncthreads();

    if (tid == 0) {
        int acc = 0;
        for (int w = 0; w < ROWW; w++) { wpre[w] = acc; acc += __popcll(kw[w]); }
        wpre[ROWW] = acc;
    }
    __syncthreads();

    for (int i = tid; i < KSEL; i += blockDim.x) {
        int w = i >> 6, b = i & 63;
        unsigned long long word = kw[w];
        if ((word >> b) & 1ull) {
            int rank = wpre[w] + __popcll(word & ((1ull << b) - 1ull));
            if (rank < MAXDET) {
                float4 bb = g_b[i];
                float* o = out + rank * 6;
                o[0] = bb.x; o[1] = bb.y; o[2] = bb.z; o[3] = bb.w;
                o[4] = g_topS[i]; o[5] = g_c[i];
            }
        }
    }
}

/* ---------------- stage 5: image BGR/CHW/255 normalize ------------------- */
__global__ void img_kernel(const int* __restrict__ img, float* __restrict__ out) {
    int idx = blockIdx.x * blockDim.x + threadIdx.x;
    if (idx >= 3 * IMG_PIX) return;
    int c = idx / IMG_PIX;
    int r = idx - c * IMG_PIX;
    int v = img[r * 3 + (2 - c)];              /* [::-1] channel flip */
    out[idx] = __fdiv_rn((float)v, 255.0f);
}

/* ---------------- launch ------------------------------------------------- */
extern "C" void kernel_launch(void* const* d_in, const int* in_sizes, int n_in,
                              void* d_out, int out_size) {
    (void)in_sizes; (void)n_in; (void)out_size;
    const int*   img  = (const int*)d_in[0];
    const float* pred = (const float*)d_in[1];   /* batch 0 only is needed */
    float* out = (float*)d_out;                  /* [det(1000*6) | x(3*640*640)] */

    prep_kernel         <<<(NN + 7) / 8, 256>>>(pred);
    topk_kernel         <<<1, 1024>>>(pred);
    mask_kernel         <<<dim3(32, 8), 256>>>();
    nms_finalize_kernel <<<1, 1024>>>(out);
    img_kernel          <<<(3 * IMG_PIX + 255) / 256, 256>>>(img, out + MAXDET * 6);
}

// round 7
// speedup vs baseline: 2.2968x; 2.2968x over previous
#include <cuda_runtime.h>

#define NN      25200
#define KSEL    2048
#define NCLS    80
#define CONF_T  0.4f
#define IOU_T   0.45f
#define MAXDET  1000
#define MAXWH   7680.0f
#define ROWW    32          /* 2048/64 uint64 words per mask row */
#define IMG_PIX (640*640)

typedef unsigned long long u64;

/* ---------------- scratch (device globals; no allocation) ---------------- */
__device__ float              g_scores[NN];
__device__ float              g_cls[NN];
__device__ unsigned           g_key32[NN];
__device__ __align__(16) float g_topS[KSEL];
__device__ float4             g_b[KSEL];      /* unshifted xyxy of sorted cands */
__device__ float              g_c[KSEL];      /* class as float */
__device__ float4             g_boff[KSEL];   /* class-offset boxes for IoU */
__device__ u64                g_maskM[KSEL * ROWW]; /* suppression bitmatrix */

/* ---------------- stage 1: per-anchor conf / cls / sortable key ---------- */
__global__ void prep_kernel(const float* __restrict__ pred) {
    int anchor = (blockIdx.x * blockDim.x + threadIdx.x) >> 5;
    int lane   = threadIdx.x & 31;
    if (anchor >= NN) return;
    const float* row = pred + (long long)anchor * 85;
    float obj = row[4];
    float best = -1.0f;
    int   bc   = 0;
    for (int j = lane; j < NCLS; j += 32) {
        float v = __fmul_rn(row[5 + j], obj);
        if (v > best) { best = v; bc = j; }       /* strict > -> first max */
    }
    /* warp argmax, ties -> lowest class index (jnp.argmax semantics) */
    for (int off = 16; off; off >>= 1) {
        float ov = __shfl_down_sync(0xffffffffu, best, off);
        int   oc = __shfl_down_sync(0xffffffffu, bc, off);
        if (ov > best || (ov == best && oc < bc)) { best = ov; bc = oc; }
    }
    if (lane == 0) {
        float s = (best > CONF_T) ? best : -1.0f;
        g_scores[anchor] = s;
        g_cls[anchor]    = (float)bc;
        unsigned u = __float_as_uint(s);
        g_key32[anchor] = (u >> 31) ? ~u : (u | 0x80000000u);  /* order-preserving */
    }
}

/* -------- stage 2: radix-select + bitonic top-2048 + fused gather -------- */
__global__ void topk_kernel(const float* __restrict__ pred) {
    __shared__ int bins[256];
    __shared__ int s_sel, s_acc, s_cnt;
    __shared__ u64 key64[KSEL];
    int tid = threadIdx.x;

    /* 4x8-bit radix select: find T = 2048th-largest key */
    unsigned prefixv = 0;
    int need = KSEL;
    for (int shift = 24; shift >= 0; shift -= 8) {
        for (int b = tid; b < 256; b += blockDim.x) bins[b] = 0;
        __syncthreads();
        unsigned hmask = (shift == 24) ? 0u : (0xFFFFFFFFu << (shift + 8));
        for (int i = tid; i < NN; i += blockDim.x) {
            unsigned k = g_key32[i];
            if ((k & hmask) == prefixv) atomicAdd(&bins[(k >> shift) & 255], 1);
        }
        __syncthreads();
        if (tid == 0) {
            int acc = 0, v = 0;
            for (int b = 255; b >= 0; b--) {
                if (acc + bins[b] >= need) { v = b; break; }
                acc += bins[b];
            }
            s_sel = v; s_acc = acc;
        }
        __syncthreads();
        prefixv |= ((unsigned)s_sel) << shift;
        need -= s_acc;
        __syncthreads();
    }

    /* gather all keys >= T (>= 2048 exist), cap at 2048 */
    if (tid == 0) s_cnt = 0;
    __syncthreads();
    for (int i = tid; i < NN; i += blockDim.x) {
        unsigned k = g_key32[i];
        if (k >= prefixv) {
            int p = atomicAdd(&s_cnt, 1);
            if (p < KSEL)
                key64[p] = (((u64)k) << 32) | (unsigned)(~(unsigned)i);
        }
    }
    __syncthreads();

    /* bitonic sort 2048 keys descending; ~index low bits => lowest index
       wins ties; gather order becomes irrelevant (deterministic) */
    for (unsigned k = 2; k <= KSEL; k <<= 1) {
        for (unsigned j = k >> 1; j; j >>= 1) {
            for (unsigned t = tid; t < KSEL; t += blockDim.x) {
                unsigned l = t ^ j;
                if (l > t) {
                    u64 a = key64[t], b = key64[l];
                    bool descBlk = ((t & k) == 0);
                    bool sw = descBlk ? (a < b) : (a > b);
                    if (sw) { key64[t] = b; key64[l] = a; }
                }
            }
            __syncthreads();
        }
    }

    /* fused gather: boxes, class offsets, scores */
    for (int t = tid; t < KSEL; t += blockDim.x) {
        u64 kk = key64[t];
        int idx = (int)(~(unsigned)(kk & 0xFFFFFFFFull));
        g_topS[t] = g_scores[idx];
        const float* row = pred + (long long)idx * 85;
        float x = row[0], y = row[1], w = row[2], h = row[3];
        float hw = __fmul_rn(w, 0.5f), hh = __fmul_rn(h, 0.5f);
        float4 b;
        b.x = __fsub_rn(x, hw); b.y = __fsub_rn(y, hh);
        b.z = __fadd_rn(x, hw); b.w = __fadd_rn(y, hh);
        float c   = g_cls[idx];
        float off = __fmul_rn(c, MAXWH);
        float4 bo;
        bo.x = __fadd_rn(b.x, off); bo.y = __fadd_rn(b.y, off);
        bo.z = __fadd_rn(b.z, off); bo.w = __fadd_rn(b.w, off);
        g_b[t] = b; g_c[t] = c; g_boff[t] = bo;
    }
}

/* -- stage 3: 2048x2048 suppression bitmask, upper-triangle words only ---- */
__global__ void mask_kernel() {
    __shared__ float4 jb[64];
    int jblk = blockIdx.x;
    /* lower-triangle words (never read by NMS): skip whole block */
    if (jblk < (int)blockIdx.y * 4) return;
    int tid = threadIdx.x;
    if (tid < 64) jb[tid] = g_boff[jblk * 64 + tid];
    __syncthreads();
    int i = blockIdx.y * 256 + tid;
    float4 a = g_boff[i];
    float areaA = __fmul_rn(__fsub_rn(a.z, a.x), __fsub_rn(a.w, a.y));
    u64 bits = 0;
    int jbase = jblk * 64;
    #pragma unroll 8
    for (int jj = 0; jj < 64; jj++) {
        int j = jbase + jj;
        if (j <= i) continue;                  /* ar > i */
        float4 bb = jb[jj];
        float lx = fmaxf(a.x, bb.x), ly = fmaxf(a.y, bb.y);
        float rx = fminf(a.z, bb.z), ry = fminf(a.w, bb.w);
        float w = fmaxf(__fsub_rn(rx, lx), 0.0f);
        float h = fmaxf(__fsub_rn(ry, ly), 0.0f);
        float inter = __fmul_rn(w, h);
        float areaB = __fmul_rn(__fsub_rn(bb.z, bb.x), __fsub_rn(bb.w, bb.y));
        float denom = __fadd_rn(__fsub_rn(__fadd_rn(areaA, areaB), inter), 1e-7f);
        float iou = __fdiv_rn(inter, denom);
        if (iou > IOU_T) bits |= (1ull << jj);
    }
    g_maskM[(long long)i * ROWW + jblk] = bits;
}

/* -- stage 4: serial NMS, 1 warp, register chain + fused finalize --------- */
__global__ void __launch_bounds__(32) nms_finalize_kernel(float* __restrict__ out) {
    __shared__ u64 sd[2][64];                  /* double-buffered diag block */
    const unsigned FULL = 0xffffffffu;
    int lane = threadIdx.x;

    /* alive bits from scores (lane owns indices [64*lane, 64*lane+64)) */
    u64 alive = 0;
    const float4* ts = (const float4*)g_topS + lane * 16;
    #pragma unroll
    for (int q = 0; q < 16; q++) {
        float4 v = ts[q];
        if (v.x > CONF_T) alive |= 1ull << (4 * q + 0);
        if (v.y > CONF_T) alive |= 1ull << (4 * q + 1);
        if (v.z > CONF_T) alive |= 1ull << (4 * q + 2);
        if (v.w > CONF_T) alive |= 1ull << (4 * q + 3);
    }

    /* preload diag block 0 (rows 0..63, word 0) */
    sd[0][2 * lane]     = g_maskM[(size_t)(2 * lane) * ROWW];
    sd[0][2 * lane + 1] = g_maskM[(size_t)(2 * lane + 1) * ROWW];
    __syncwarp();

    int buf = 0;
    for (int w = 0; w < ROWW; w++) {
        /* prefetch next diag block into regs (latency hides under the chain) */
        u64 p0 = 0, p1 = 0;
        if (w + 1 < ROWW) {
            p0 = g_maskM[(size_t)((w + 1) * 64 + 2 * lane)     * ROWW + (w + 1)];
            p1 = g_maskM[(size_t)((w + 1) * 64 + 2 * lane + 1) * ROWW + (w + 1)];
        }

        u64 aw = __shfl_sync(FULL, alive, w);   /* current alive word w */
        u64 sup = 0;
        const u64* colp = g_maskM + (size_t)(w * 64) * ROWW + lane;
        bool doCol = lane > w;                  /* words <= w have no j>i bits */

        #pragma unroll
        for (int c = 0; c < 4; c++) {
            /* issue this chunk's column loads before the chain needs masks */
            u64 cl[16];
            #pragma unroll
            for (int k = 0; k < 16; k++)
                cl[k] = doCol ? colp[(size_t)(c * 16 + k) * ROWW] : 0ull;
            /* diag chunk from smem (broadcast, conflict-free) */
            u64 t[16];
            #pragma unroll
            for (int k = 0; k < 16; k++) t[k] = sd[buf][c * 16 + k];
            /* serial greedy chain: 3-op dependent step, all in registers.
               Redundant in every lane -> no divergence, no decision shfl. */
            #pragma unroll
            for (int k = 0; k < 16; k++) {
                int b = c * 16 + k;
                u64 m = (u64)((long long)(aw << (63 - b)) >> 63);
                aw &= ~(t[k] & m);
            }
            /* aw bits of this chunk are now final (rows only carry j>i bits):
               use them as decision masks for the column apply */
            #pragma unroll
            for (int k = 0; k < 16; k++) {
                int b = c * 16 + k;
                u64 m = (u64)((long long)(aw << (63 - b)) >> 63);
                sup |= cl[k] & m;
            }
        }

        if (lane == w)      alive = aw;         /* diag word finalized */
        else if (doCol)     alive &= ~sup;      /* idempotent-safe apply */

        if (w + 1 < ROWW) {
            sd[buf ^ 1][2 * lane]     = p0;
            sd[buf ^ 1][2 * lane + 1] = p1;
        }
        __syncwarp();
        buf ^= 1;
    }

    /* ---- fused finalize: warp scan + per-lane survivor emit ---- */
    float4* o4 = (float4*)out;
    for (int q = lane; q < MAXDET * 6 / 4; q += 32)
        o4[q] = make_float4(0.f, 0.f, 0.f, 0.f);
    __syncwarp();

    int cnt = __popcll(alive);
    int pre = cnt;
    #pragma unroll
    for (int off = 1; off < 32; off <<= 1) {
        int v = __shfl_up_sync(FULL, pre, off);
        if (lane >= off) pre += v;
    }
    pre -= cnt;                                 /* exclusive prefix */

    u64 a = alive;
    while (a) {
        int b = __ffsll((long long)a) - 1;
        a &= a - 1;
        int i = lane * 64 + b;
        int rank = pre++;
        if (rank < MAXDET) {
            float4 bb = g_b[i];
            float* o = out + rank * 6;
            o[0] = bb.x; o[1] = bb.y; o[2] = bb.z; o[3] = bb.w;
            o[4] = g_topS[i]; o[5] = g_c[i];
        }
    }
}

/* ---------------- stage 5: image BGR/CHW/255, coalesced ------------------ */
__global__ void img_kernel(const int* __restrict__ img, float* __restrict__ out) {
    int r = blockIdx.x * blockDim.x + threadIdx.x;
    if (r >= IMG_PIX) return;
    int b = img[3 * r], g = img[3 * r + 1], rr = img[3 * r + 2];
    out[r]               = __fdiv_rn((float)rr, 255.0f);  /* [::-1] flip */
    out[IMG_PIX + r]     = __fdiv_rn((float)g,  255.0f);
    out[2 * IMG_PIX + r] = __fdiv_rn((float)b,  255.0f);
}

/* ---------------- launch ------------------------------------------------- */
extern "C" void kernel_launch(void* const* d_in, const int* in_sizes, int n_in,
                              void* d_out, int out_size) {
    (void)in_sizes; (void)n_in; (void)out_size;
    const int*   img  = (const int*)d_in[0];
    const float* pred = (const float*)d_in[1];   /* batch 0 only is needed */
    float* out = (float*)d_out;                  /* [det(1000*6) | x(3*640*640)] */

    prep_kernel         <<<(NN + 7) / 8, 256>>>(pred);
    topk_kernel         <<<1, 1024>>>(pred);
    mask_kernel         <<<dim3(32, 8), 256>>>();
    nms_finalize_kernel <<<1, 32>>>(out);
    img_kernel          <<<(IMG_PIX + 255) / 256, 256>>>(img, out + MAXDET * 6);
}

// round 8
// speedup vs baseline: 2.9485x; 1.2837x over previous
#include <cuda_runtime.h>

#define NN      25200
#define KSEL    2048
#define NCLS    80
#define CONF_T  0.4f
#define IOU_T   0.45f
#define MAXDET  1000
#define MAXWH   7680.0f
#define ROWW    32          /* 2048/64 uint64 words per mask row */
#define IMG_PIX (640*640)

typedef unsigned long long u64;

/* ---------------- scratch (device globals; no allocation) ---------------- */
__device__ float              g_scores[NN];
__device__ float              g_cls[NN];
__device__ unsigned           g_key32[NN];
__device__ __align__(16) float g_topS[KSEL];
__device__ float4             g_b[KSEL];      /* unshifted xyxy of sorted cands */
__device__ float              g_c[KSEL];      /* class as float */
__device__ float4             g_boff[KSEL];   /* class-offset boxes for IoU */
__device__ u64                g_maskM[KSEL * ROWW]; /* suppression bitmatrix */
__device__ unsigned           g_nz[ROWW];     /* bit j of word w: block(w,j) nonzero */

/* ---------------- stage 1: per-anchor conf / cls / sortable key ---------- */
__global__ void prep_kernel(const float* __restrict__ pred) {
    if (blockIdx.x == 0 && threadIdx.x < ROWW) g_nz[threadIdx.x] = 0;
    int anchor = (blockIdx.x * blockDim.x + threadIdx.x) >> 5;
    int lane   = threadIdx.x & 31;
    if (anchor >= NN) return;
    const float* row = pred + (long long)anchor * 85;
    float obj = row[4];
    float best = -1.0f;
    int   bc   = 0;
    for (int j = lane; j < NCLS; j += 32) {
        float v = __fmul_rn(row[5 + j], obj);
        if (v > best) { best = v; bc = j; }       /* strict > -> first max */
    }
    /* warp argmax, ties -> lowest class index (jnp.argmax semantics) */
    for (int off = 16; off; off >>= 1) {
        float ov = __shfl_down_sync(0xffffffffu, best, off);
        int   oc = __shfl_down_sync(0xffffffffu, bc, off);
        if (ov > best || (ov == best && oc < bc)) { best = ov; bc = oc; }
    }
    if (lane == 0) {
        float s = (best > CONF_T) ? best : -1.0f;
        g_scores[anchor] = s;
        g_cls[anchor]    = (float)bc;
        unsigned u = __float_as_uint(s);
        g_key32[anchor] = (u >> 31) ? ~u : (u | 0x80000000u);  /* order-preserving */
    }
}

/* -------- stage 2: radix-select + bitonic top-2048 + fused gather -------- */
__global__ void topk_kernel(const float* __restrict__ pred) {
    __shared__ int bins[256];
    __shared__ int s_sel, s_acc, s_cnt;
    __shared__ u64 key64[KSEL];
    int tid = threadIdx.x;

    /* 4x8-bit radix select: find T = 2048th-largest key */
    unsigned prefixv = 0;
    int need = KSEL;
    for (int shift = 24; shift >= 0; shift -= 8) {
        for (int b = tid; b < 256; b += blockDim.x) bins[b] = 0;
        __syncthreads();
        unsigned hmask = (shift == 24) ? 0u : (0xFFFFFFFFu << (shift + 8));
        for (int i = tid; i < NN; i += blockDim.x) {
            unsigned k = g_key32[i];
            if ((k & hmask) == prefixv) atomicAdd(&bins[(k >> shift) & 255], 1);
        }
        __syncthreads();
        if (tid == 0) {
            int acc = 0, v = 0;
            for (int b = 255; b >= 0; b--) {
                if (acc + bins[b] >= need) { v = b; break; }
                acc += bins[b];
            }
            s_sel = v; s_acc = acc;
        }
        __syncthreads();
        prefixv |= ((unsigned)s_sel) << shift;
        need -= s_acc;
        __syncthreads();
    }

    /* gather all keys >= T (>= 2048 exist), cap at 2048 */
    if (tid == 0) s_cnt = 0;
    __syncthreads();
    for (int i = tid; i < NN; i += blockDim.x) {
        unsigned k = g_key32[i];
        if (k >= prefixv) {
            int p = atomicAdd(&s_cnt, 1);
            if (p < KSEL)
                key64[p] = (((u64)k) << 32) | (unsigned)(~(unsigned)i);
        }
    }
    __syncthreads();

    /* bitonic sort 2048 keys descending; ~index low bits => lowest index
       wins ties; gather order becomes irrelevant (deterministic) */
    for (unsigned k = 2; k <= KSEL; k <<= 1) {
        for (unsigned j = k >> 1; j; j >>= 1) {
            for (unsigned t = tid; t < KSEL; t += blockDim.x) {
                unsigned l = t ^ j;
                if (l > t) {
                    u64 a = key64[t], b = key64[l];
                    bool descBlk = ((t & k) == 0);
                    bool sw = descBlk ? (a < b) : (a > b);
                    if (sw) { key64[t] = b; key64[l] = a; }
                }
            }
            __syncthreads();
        }
    }

    /* fused gather: boxes, class offsets, scores */
    for (int t = tid; t < KSEL; t += blockDim.x) {
        u64 kk = key64[t];
        int idx = (int)(~(unsigned)(kk & 0xFFFFFFFFull));
        g_topS[t] = g_scores[idx];
        const float* row = pred + (long long)idx * 85;
        float x = row[0], y = row[1], w = row[2], h = row[3];
        float hw = __fmul_rn(w, 0.5f), hh = __fmul_rn(h, 0.5f);
        float4 b;
        b.x = __fsub_rn(x, hw); b.y = __fsub_rn(y, hh);
        b.z = __fadd_rn(x, hw); b.w = __fadd_rn(y, hh);
        float c   = g_cls[idx];
        float off = __fmul_rn(c, MAXWH);
        float4 bo;
        bo.x = __fadd_rn(b.x, off); bo.y = __fadd_rn(b.y, off);
        bo.z = __fadd_rn(b.z, off); bo.w = __fadd_rn(b.w, off);
        g_b[t] = b; g_c[t] = c; g_boff[t] = bo;
    }
}

/* -- stage 3: suppression bitmask (upper-tri words) + nonzero summary ----- */
__global__ void mask_kernel() {
    __shared__ float4 jb[64];
    int jblk = blockIdx.x;
    /* lower-triangle words (never read by NMS): skip whole block */
    if (jblk < (int)blockIdx.y * 4) return;
    int tid = threadIdx.x;
    if (tid < 64) jb[tid] = g_boff[jblk * 64 + tid];
    __syncthreads();
    int i = blockIdx.y * 256 + tid;
    float4 a = g_boff[i];
    float areaA = __fmul_rn(__fsub_rn(a.z, a.x), __fsub_rn(a.w, a.y));
    u64 bits = 0;
    int jbase = jblk * 64;
    #pragma unroll 8
    for (int jj = 0; jj < 64; jj++) {
        int j = jbase + jj;
        if (j <= i) continue;                  /* ar > i */
        float4 bb = jb[jj];
        float lx = fmaxf(a.x, bb.x), ly = fmaxf(a.y, bb.y);
        float rx = fminf(a.z, bb.z), ry = fminf(a.w, bb.w);
        float w = fmaxf(__fsub_rn(rx, lx), 0.0f);
        float h = fmaxf(__fsub_rn(ry, ly), 0.0f);
        float inter = __fmul_rn(w, h);
        float areaB = __fmul_rn(__fsub_rn(bb.z, bb.x), __fsub_rn(bb.w, bb.y));
        float denom = __fadd_rn(__fsub_rn(__fadd_rn(areaA, areaB), inter), 1e-7f);
        float iou = __fdiv_rn(inter, denom);
        if (iou > IOU_T) bits |= (1ull << jj);
    }
    g_maskM[(long long)i * ROWW + jblk] = bits;
    if (bits) atomicOr(&g_nz[i >> 6], 1u << jblk);
}

/* -- stage 4: sparse serial NMS (1 warp) + fused finalize ----------------- */
__global__ void __launch_bounds__(32) nms_finalize_kernel(float* __restrict__ out) {
    __shared__ u64 sd[64];                     /* diag block staging */
    __shared__ unsigned snz[32];
    const unsigned FULL = 0xffffffffu;
    int lane = threadIdx.x;

    snz[lane] = g_nz[lane];

    /* alive bits from scores (lane owns indices [64*lane, 64*lane+64)) */
    u64 alive = 0;
    const float4* ts = (const float4*)g_topS + lane * 16;
    #pragma unroll
    for (int q = 0; q < 16; q++) {
        float4 v = ts[q];
        if (v.x > CONF_T) alive |= 1ull << (4 * q + 0);
        if (v.y > CONF_T) alive |= 1ull << (4 * q + 1);
        if (v.z > CONF_T) alive |= 1ull << (4 * q + 2);
        if (v.w > CONF_T) alive |= 1ull << (4 * q + 3);
    }
    __syncwarp();

    for (int w = 0; w < ROWW; w++) {
        unsigned nzw = snz[w];                 /* uniform across warp */
        u64 aw = __shfl_sync(FULL, alive, w);

        if (nzw & (1u << w)) {
            /* diag block nonzero: cooperative load, redundant register chain */
            sd[2 * lane]     = g_maskM[(size_t)(w * 64 + 2 * lane)     * ROWW + w];
            sd[2 * lane + 1] = g_maskM[(size_t)(w * 64 + 2 * lane + 1) * ROWW + w];
            __syncwarp();
            #pragma unroll
            for (int c = 0; c < 4; c++) {
                u64 t[16];
                #pragma unroll
                for (int k = 0; k < 16; k++) t[k] = sd[c * 16 + k];
                #pragma unroll
                for (int k = 0; k < 16; k++) {
                    int b = c * 16 + k;
                    u64 m = (u64)((long long)(aw << (63 - b)) >> 63);
                    aw &= ~(t[k] & m);
                }
            }
            __syncwarp();
        }
        /* aw is now final for word w (rows carry only j>i bits) */
        if (lane == w) {
            alive = aw;
        } else if (lane > w && (nzw & (1u << lane))) {
            /* column block nonzero: apply decided suppressions */
            const u64* colp = g_maskM + (size_t)(w * 64) * ROWW + lane;
            u64 sup = 0;
            #pragma unroll 8
            for (int b = 0; b < 64; b++) {
                u64 m = (u64)((long long)(aw << (63 - b)) >> 63);
                sup |= colp[(size_t)b * ROWW] & m;
            }
            alive &= ~sup;
        }
    }

    /* ---- fused finalize: warp scan + per-lane survivor emit ---- */
    float4* o4 = (float4*)out;
    for (int q = lane; q < MAXDET * 6 / 4; q += 32)
        o4[q] = make_float4(0.f, 0.f, 0.f, 0.f);
    __syncwarp();

    int cnt = __popcll(alive);
    int pre = cnt;
    #pragma unroll
    for (int off = 1; off < 32; off <<= 1) {
        int v = __shfl_up_sync(FULL, pre, off);
        if (lane >= off) pre += v;
    }
    pre -= cnt;                                 /* exclusive prefix */

    u64 a = alive;
    while (a) {
        int b = __ffsll((long long)a) - 1;
        a &= a - 1;
        int i = lane * 64 + b;
        int rank = pre++;
        if (rank < MAXDET) {
            float4 bb = g_b[i];
            float* o = out + rank * 6;
            o[0] = bb.x; o[1] = bb.y; o[2] = bb.z; o[3] = bb.w;
            o[4] = g_topS[i]; o[5] = g_c[i];
        }
    }
}

/* ---------------- stage 5: image BGR/CHW/255, coalesced ------------------ */
__global__ void img_kernel(const int* __restrict__ img, float* __restrict__ out) {
    int r = blockIdx.x * blockDim.x + threadIdx.x;
    if (r >= IMG_PIX) return;
    int b = img[3 * r], g = img[3 * r + 1], rr = img[3 * r + 2];
    out[r]               = __fdiv_rn((float)rr, 255.0f);  /* [::-1] flip */
    out[IMG_PIX + r]     = __fdiv_rn((float)g,  255.0f);
    out[2 * IMG_PIX + r] = __fdiv_rn((float)b,  255.0f);
}

/* ---------------- launch ------------------------------------------------- */
extern "C" void kernel_launch(void* const* d_in, const int* in_sizes, int n_in,
                              void* d_out, int out_size) {
    (void)in_sizes; (void)n_in; (void)out_size;
    const int*   img  = (const int*)d_in[0];
    const float* pred = (const float*)d_in[1];   /* batch 0 only is needed */
    float* out = (float*)d_out;                  /* [det(1000*6) | x(3*640*640)] */

    prep_kernel         <<<(NN + 7) / 8, 256>>>(pred);
    topk_kernel         <<<1, 1024>>>(pred);
    mask_kernel         <<<dim3(32, 8), 256>>>();
    nms_finalize_kernel <<<1, 32>>>(out);
    img_kernel          <<<(IMG_PIX + 255) / 256, 256>>>(img, out + MAXDET * 6);
}

// round 9
// speedup vs baseline: 3.4820x; 1.1809x over previous
#include <cuda_runtime.h>

#define NN      25200
#define KSEL    2048
#define NCLS    80
#define CONF_T  0.4f
#define IOU_T   0.45f
#define MAXDET  1000
#define MAXWH   7680.0f
#define ROWW    32          /* 2048/64 uint64 words per mask row */
#define IMG_PIX (640*640)
#define ECAP    2048        /* sparse edge-list capacity */

typedef unsigned long long u64;

/* ---------------- scratch (device globals; no allocation) ---------------- */
__device__ float              g_scores[NN];
__device__ float              g_cls[NN];
__device__ unsigned           g_key32[NN];
__device__ __align__(16) float g_topS[KSEL];
__device__ float4             g_b[KSEL];      /* unshifted xyxy of sorted cands */
__device__ float              g_c[KSEL];      /* class as float */
__device__ float4             g_boff[KSEL];   /* class-offset boxes for IoU */
__device__ u64                g_maskM[KSEL * ROWW]; /* dense fallback matrix */
__device__ unsigned           g_nz[ROWW];     /* block-nonzero bitmap (fallback) */
__device__ int                g_edgeCnt;
__device__ unsigned           g_edges[ECAP];  /* (i<<12)|j suppression pairs */

/* ---------------- stage 1: per-anchor conf / cls / sortable key ---------- */
__global__ void prep_kernel(const float* __restrict__ pred) {
    if (blockIdx.x == 0) {
        if (threadIdx.x < ROWW) g_nz[threadIdx.x] = 0;
        if (threadIdx.x == 0)   g_edgeCnt = 0;
    }
    int anchor = (blockIdx.x * blockDim.x + threadIdx.x) >> 5;
    int lane   = threadIdx.x & 31;
    if (anchor >= NN) return;
    const float* row = pred + (long long)anchor * 85;
    float obj = row[4];
    float best = -1.0f;
    int   bc   = 0;
    for (int j = lane; j < NCLS; j += 32) {
        float v = __fmul_rn(row[5 + j], obj);
        if (v > best) { best = v; bc = j; }       /* strict > -> first max */
    }
    /* warp argmax, ties -> lowest class index (jnp.argmax semantics) */
    for (int off = 16; off; off >>= 1) {
        float ov = __shfl_down_sync(0xffffffffu, best, off);
        int   oc = __shfl_down_sync(0xffffffffu, bc, off);
        if (ov > best || (ov == best && oc < bc)) { best = ov; bc = oc; }
    }
    if (lane == 0) {
        float s = (best > CONF_T) ? best : -1.0f;
        g_scores[anchor] = s;
        g_cls[anchor]    = (float)bc;
        unsigned u = __float_as_uint(s);
        g_key32[anchor] = (u >> 31) ? ~u : (u | 0x80000000u);  /* order-preserving */
    }
}

/* -------- stage 2: radix-select + bitonic top-2048 + fused gather -------- */
__global__ void topk_kernel(const float* __restrict__ pred) {
    __shared__ int bins[256];
    __shared__ int s_sel, s_acc, s_cnt;
    __shared__ u64 key64[KSEL];
    int tid = threadIdx.x;

    /* 4x8-bit radix select: find T = 2048th-largest key */
    unsigned prefixv = 0;
    int need = KSEL;
    for (int shift = 24; shift >= 0; shift -= 8) {
        for (int b = tid; b < 256; b += blockDim.x) bins[b] = 0;
        __syncthreads();
        unsigned hmask = (shift == 24) ? 0u : (0xFFFFFFFFu << (shift + 8));
        for (int i = tid; i < NN; i += blockDim.x) {
            unsigned k = g_key32[i];
            if ((k & hmask) == prefixv) atomicAdd(&bins[(k >> shift) & 255], 1);
        }
        __syncthreads();
        if (tid == 0) {
            int acc = 0, v = 0;
            for (int b = 255; b >= 0; b--) {
                if (acc + bins[b] >= need) { v = b; break; }
                acc += bins[b];
            }
            s_sel = v; s_acc = acc;
        }
        __syncthreads();
        prefixv |= ((unsigned)s_sel) << shift;
        need -= s_acc;
        __syncthreads();
    }

    /* gather all keys >= T (>= 2048 exist), cap at 2048 */
    if (tid == 0) s_cnt = 0;
    __syncthreads();
    for (int i = tid; i < NN; i += blockDim.x) {
        unsigned k = g_key32[i];
        if (k >= prefixv) {
            int p = atomicAdd(&s_cnt, 1);
            if (p < KSEL)
                key64[p] = (((u64)k) << 32) | (unsigned)(~(unsigned)i);
        }
    }
    __syncthreads();

    /* bitonic sort 2048 keys descending; ~index low bits => lowest index
       wins ties; gather order becomes irrelevant (deterministic) */
    for (unsigned k = 2; k <= KSEL; k <<= 1) {
        for (unsigned j = k >> 1; j; j >>= 1) {
            for (unsigned t = tid; t < KSEL; t += blockDim.x) {
                unsigned l = t ^ j;
                if (l > t) {
                    u64 a = key64[t], b = key64[l];
                    bool descBlk = ((t & k) == 0);
                    bool sw = descBlk ? (a < b) : (a > b);
                    if (sw) { key64[t] = b; key64[l] = a; }
                }
            }
            __syncthreads();
        }
    }

    /* fused gather: boxes, class offsets, scores */
    for (int t = tid; t < KSEL; t += blockDim.x) {
        u64 kk = key64[t];
        int idx = (int)(~(unsigned)(kk & 0xFFFFFFFFull));
        g_topS[t] = g_scores[idx];
        const float* row = pred + (long long)idx * 85;
        float x = row[0], y = row[1], w = row[2], h = row[3];
        float hw = __fmul_rn(w, 0.5f), hh = __fmul_rn(h, 0.5f);
        float4 b;
        b.x = __fsub_rn(x, hw); b.y = __fsub_rn(y, hh);
        b.z = __fadd_rn(x, hw); b.w = __fadd_rn(y, hh);
        float c   = g_cls[idx];
        float off = __fmul_rn(c, MAXWH);
        float4 bo;
        bo.x = __fadd_rn(b.x, off); bo.y = __fadd_rn(b.y, off);
        bo.z = __fadd_rn(b.z, off); bo.w = __fadd_rn(b.w, off);
        g_b[t] = b; g_c[t] = c; g_boff[t] = bo;
    }
}

/* -- stage 3: suppression mask -> sparse edges + dense fallback ----------- */
__global__ void mask_kernel() {
    __shared__ float4 jb[64];
    int jblk = blockIdx.x;
    /* lower-triangle words (never read) : skip whole block */
    if (jblk < (int)blockIdx.y * 4) return;
    int tid = threadIdx.x;
    if (tid < 64) jb[tid] = g_boff[jblk * 64 + tid];
    __syncthreads();
    int i = blockIdx.y * 256 + tid;
    float4 a = g_boff[i];
    float areaA = __fmul_rn(__fsub_rn(a.z, a.x), __fsub_rn(a.w, a.y));
    u64 bits = 0;
    int jbase = jblk * 64;
    #pragma unroll 8
    for (int jj = 0; jj < 64; jj++) {
        int j = jbase + jj;
        if (j <= i) continue;                  /* ar > i */
        float4 bb = jb[jj];
        float lx = fmaxf(a.x, bb.x), ly = fmaxf(a.y, bb.y);
        float rx = fminf(a.z, bb.z), ry = fminf(a.w, bb.w);
        float w = fmaxf(__fsub_rn(rx, lx), 0.0f);
        float h = fmaxf(__fsub_rn(ry, ly), 0.0f);
        float inter = __fmul_rn(w, h);
        float areaB = __fmul_rn(__fsub_rn(bb.z, bb.x), __fsub_rn(bb.w, bb.y));
        float denom = __fadd_rn(__fsub_rn(__fadd_rn(areaA, areaB), inter), 1e-7f);
        float iou = __fdiv_rn(inter, denom);
        if (iou > IOU_T) {
            bits |= (1ull << jj);
            int p = atomicAdd(&g_edgeCnt, 1);           /* rare (~60 total) */
            if (p < ECAP)
                g_edges[p] = (((unsigned)i) << 12) | (unsigned)j;
        }
    }
    g_maskM[(long long)i * ROWW + jblk] = bits;
    if (bits) atomicOr(&g_nz[i >> 6], 1u << jblk);
}

/* -- stage 4: sparse-edge serial NMS (1 warp) + fused finalize ------------ */
__global__ void __launch_bounds__(32) nms_finalize_kernel(float* __restrict__ out) {
    __shared__ unsigned se[ECAP];              /* sorted edge keys */
    __shared__ u64      sm_alive[ROWW];
    __shared__ u64      sd[64];
    __shared__ unsigned snz[32];
    const unsigned FULL = 0xffffffffu;
    int lane = threadIdx.x;

    int cnt = g_edgeCnt;                       /* same addr -> broadcast load */

    /* alive bits from scores (lane owns indices [64*lane, 64*lane+64)) */
    u64 alive = 0;
    const float4* ts = (const float4*)g_topS + lane * 16;
    #pragma unroll
    for (int q = 0; q < 16; q++) {
        float4 v = ts[q];
        if (v.x > CONF_T) alive |= 1ull << (4 * q + 0);
        if (v.y > CONF_T) alive |= 1ull << (4 * q + 1);
        if (v.z > CONF_T) alive |= 1ull << (4 * q + 2);
        if (v.w > CONF_T) alive |= 1ull << (4 * q + 3);
    }

    if (cnt <= ECAP) {
        /* ---------- sparse path: sort edges, serial greedy over list ------ */
        int P = 32;
        while (P < cnt) P <<= 1;
        for (int t = lane; t < P; t += 32)
            se[t] = (t < cnt) ? g_edges[t] : 0xFFFFFFFFu;
        sm_alive[lane] = alive;
        __syncwarp();
        /* bitonic ascending: groups by i, ascending i (exact greedy order) */
        for (int k = 2; k <= P; k <<= 1) {
            for (int j2 = k >> 1; j2; j2 >>= 1) {
                for (int t = lane; t < P; t += 32) {
                    int l = t ^ j2;
                    if (l > t) {
                        unsigned a = se[t], b = se[l];
                        bool up = ((t & k) == 0);
                        if (up ? (a > b) : (a < b)) { se[t] = b; se[l] = a; }
                    }
                }
                __syncwarp();
            }
        }
        if (lane == 0) {
            for (int e = 0; e < cnt; e++) {
                unsigned k = se[e];
                int i = k >> 12, j = k & 0xFFF;
                if ((sm_alive[i >> 6] >> (i & 63)) & 1ull)
                    sm_alive[j >> 6] &= ~(1ull << (j & 63));
            }
        }
        __syncwarp();
        alive = sm_alive[lane];
    } else {
        /* ---------- dense fallback: block-sparse bitmatrix walk ----------- */
        snz[lane] = g_nz[lane];
        __syncwarp();
        for (int w = 0; w < ROWW; w++) {
            unsigned nzw = snz[w];
            u64 aw = __shfl_sync(FULL, alive, w);
            if (nzw & (1u << w)) {
                sd[2 * lane]     = g_maskM[(size_t)(w * 64 + 2 * lane)     * ROWW + w];
                sd[2 * lane + 1] = g_maskM[(size_t)(w * 64 + 2 * lane + 1) * ROWW + w];
                __syncwarp();
                #pragma unroll
                for (int c = 0; c < 4; c++) {
                    u64 t[16];
                    #pragma unroll
                    for (int k = 0; k < 16; k++) t[k] = sd[c * 16 + k];
                    #pragma unroll
                    for (int k = 0; k < 16; k++) {
                        int b = c * 16 + k;
                        u64 m = (u64)((long long)(aw << (63 - b)) >> 63);
                        aw &= ~(t[k] & m);
                    }
                }
                __syncwarp();
            }
            if (lane == w) {
                alive = aw;
            } else if (lane > w && (nzw & (1u << lane))) {
                const u64* colp = g_maskM + (size_t)(w * 64) * ROWW + lane;
                u64 cl[64];
                #pragma unroll                   /* full batch -> one round trip */
                for (int b = 0; b < 64; b++) cl[b] = colp[(size_t)b * ROWW];
                u64 sup = 0;
                #pragma unroll
                for (int b = 0; b < 64; b++) {
                    u64 m = (u64)((long long)(aw << (63 - b)) >> 63);
                    sup |= cl[b] & m;
                }
                alive &= ~sup;
            }
        }
    }

    /* ---- fused finalize: warp scan + per-lane survivor emit ---- */
    float4* o4 = (float4*)out;
    for (int q = lane; q < MAXDET * 6 / 4; q += 32)
        o4[q] = make_float4(0.f, 0.f, 0.f, 0.f);
    __syncwarp();

    int c2 = __popcll(alive);
    int pre = c2;
    #pragma unroll
    for (int off = 1; off < 32; off <<= 1) {
        int v = __shfl_up_sync(FULL, pre, off);
        if (lane >= off) pre += v;
    }
    pre -= c2;                                  /* exclusive prefix */

    u64 a = alive;
    while (a) {
        int b = __ffsll((long long)a) - 1;
        a &= a - 1;
        int i = lane * 64 + b;
        int rank = pre++;
        if (rank < MAXDET) {
            float4 bb = g_b[i];
            float* o = out + rank * 6;
            o[0] = bb.x; o[1] = bb.y; o[2] = bb.z; o[3] = bb.w;
            o[4] = g_topS[i]; o[5] = g_c[i];
        }
    }
}

/* ---------------- stage 5: image BGR/CHW/255, coalesced ------------------ */
__global__ void img_kernel(const int* __restrict__ img, float* __restrict__ out) {
    int r = blockIdx.x * blockDim.x + threadIdx.x;
    if (r >= IMG_PIX) return;
    int b = img[3 * r], g = img[3 * r + 1], rr = img[3 * r + 2];
    out[r]               = __fdiv_rn((float)rr, 255.0f);  /* [::-1] flip */
    out[IMG_PIX + r]     = __fdiv_rn((float)g,  255.0f);
    out[2 * IMG_PIX + r] = __fdiv_rn((float)b,  255.0f);
}

/* ---------------- launch ------------------------------------------------- */
extern "C" void kernel_launch(void* const* d_in, const int* in_sizes, int n_in,
                              void* d_out, int out_size) {
    (void)in_sizes; (void)n_in; (void)out_size;
    const int*   img  = (const int*)d_in[0];
    const float* pred = (const float*)d_in[1];   /* batch 0 only is needed */
    float* out = (float*)d_out;                  /* [det(1000*6) | x(3*640*640)] */

    prep_kernel         <<<(NN + 7) / 8, 256>>>(pred);
    topk_kernel         <<<1, 1024>>>(pred);
    mask_kernel         <<<dim3(32, 8), 256>>>();
    nms_finalize_kernel <<<1, 32>>>(out);
    img_kernel          <<<(IMG_PIX + 255) / 256, 256>>>(img, out + MAXDET * 6);
}

// round 10
// speedup vs baseline: 3.6294x; 1.0423x over previous
#include <cuda_runtime.h>

#define NN      25200
#define KSEL    2048
#define NCLS    80
#define CONF_T  0.4f
#define IOU_T   0.45f
#define MAXDET  1000
#define MAXWH   7680.0f
#define ROWW    32          /* 2048/64 uint64 words per mask row */
#define IMG_PIX (640*640)
#define ECAP    2048        /* sparse edge-list capacity */

typedef unsigned long long u64;

/* ---------------- scratch (device globals; no allocation) ---------------- */
__device__ float              g_scores[NN];
__device__ float              g_cls[NN];
__device__ unsigned           g_key32[NN];
__device__ __align__(16) float g_topS[KSEL];
__device__ float4             g_b[KSEL];      /* unshifted xyxy of sorted cands */
__device__ float              g_c[KSEL];      /* class as float */
__device__ float4             g_boff[KSEL];   /* class-offset boxes for IoU */
__device__ u64                g_maskM[KSEL * ROWW]; /* dense fallback matrix */
__device__ unsigned           g_nz[ROWW];     /* block-nonzero bitmap (fallback) */
__device__ int                g_edgeCnt;
__device__ unsigned           g_edges[ECAP];  /* (i<<12)|j suppression pairs */

/* ---------------- stage 1: per-anchor conf / cls / sortable key ---------- */
__global__ void prep_kernel(const float* __restrict__ pred) {
    if (blockIdx.x == 0) {
        if (threadIdx.x < ROWW) g_nz[threadIdx.x] = 0;
        if (threadIdx.x == 0)   g_edgeCnt = 0;
    }
    int anchor = (blockIdx.x * blockDim.x + threadIdx.x) >> 5;
    int lane   = threadIdx.x & 31;
    if (anchor >= NN) return;
    const float* row = pred + (long long)anchor * 85;
    float obj = row[4];
    float best = -1.0f;
    int   bc   = 0;
    for (int j = lane; j < NCLS; j += 32) {
        float v = __fmul_rn(row[5 + j], obj);
        if (v > best) { best = v; bc = j; }       /* strict > -> first max */
    }
    /* warp argmax, ties -> lowest class index (jnp.argmax semantics) */
    for (int off = 16; off; off >>= 1) {
        float ov = __shfl_down_sync(0xffffffffu, best, off);
        int   oc = __shfl_down_sync(0xffffffffu, bc, off);
        if (ov > best || (ov == best && oc < bc)) { best = ov; bc = oc; }
    }
    if (lane == 0) {
        float s = (best > CONF_T) ? best : -1.0f;
        g_scores[anchor] = s;
        g_cls[anchor]    = (float)bc;
        unsigned u = __float_as_uint(s);
        g_key32[anchor] = (u >> 31) ? ~u : (u | 0x80000000u);  /* order-preserving */
    }
}

/* -------- stage 2: radix-select + bitonic top-2048 + fused gather -------- */
__global__ void topk_kernel(const float* __restrict__ pred) {
    __shared__ int bins[256];
    __shared__ int s_sel, s_acc, s_cnt;
    __shared__ u64 key64[KSEL];
    const unsigned FULL = 0xffffffffu;
    int tid = threadIdx.x;

    /* 4x8-bit radix select: find T = 2048th-largest key.
       match_any dedups hot bins -> 1 atomic per distinct bin per warp. */
    unsigned prefixv = 0;
    int need = KSEL;
    for (int shift = 24; shift >= 0; shift -= 8) {
        for (int b = tid; b < 256; b += blockDim.x) bins[b] = 0;
        __syncthreads();
        unsigned hmask = (shift == 24) ? 0u : (0xFFFFFFFFu << (shift + 8));
        for (int base = 0; base < NN; base += blockDim.x) {
            int i = base + tid;
            bool in = (i < NN);
            unsigned k = in ? g_key32[i] : 0u;
            bool act = in && ((k & hmask) == prefixv);
            unsigned bin = (k >> shift) & 255u;
            unsigned active = __ballot_sync(FULL, act);
            if (act) {
                unsigned grp = __match_any_sync(active, bin);
                if ((tid & 31) == (__ffs(grp) - 1))
                    atomicAdd(&bins[bin], __popc(grp));
            }
        }
        __syncthreads();
        if (tid == 0) {
            int acc = 0, v = 0;
            for (int b = 255; b >= 0; b--) {
                if (acc + bins[b] >= need) { v = b; break; }
                acc += bins[b];
            }
            s_sel = v; s_acc = acc;
        }
        __syncthreads();
        prefixv |= ((unsigned)s_sel) << shift;
        need -= s_acc;
        __syncthreads();
    }

    /* gather all keys >= T (>= 2048 exist), cap at 2048 */
    if (tid == 0) s_cnt = 0;
    __syncthreads();
    for (int i = tid; i < NN; i += blockDim.x) {
        unsigned k = g_key32[i];
        if (k >= prefixv) {
            int p = atomicAdd(&s_cnt, 1);
            if (p < KSEL)
                key64[p] = (((u64)k) << 32) | (unsigned)(~(unsigned)i);
        }
    }
    __syncthreads();

    /* bitonic sort 2048 keys descending; ~index low bits => lowest index
       wins ties; gather order becomes irrelevant (deterministic) */
    for (unsigned k = 2; k <= KSEL; k <<= 1) {
        for (unsigned j = k >> 1; j; j >>= 1) {
            for (unsigned t = tid; t < KSEL; t += blockDim.x) {
                unsigned l = t ^ j;
                if (l > t) {
                    u64 a = key64[t], b = key64[l];
                    bool descBlk = ((t & k) == 0);
                    bool sw = descBlk ? (a < b) : (a > b);
                    if (sw) { key64[t] = b; key64[l] = a; }
                }
            }
            __syncthreads();
        }
    }

    /* fused gather: boxes, class offsets, scores */
    for (int t = tid; t < KSEL; t += blockDim.x) {
        u64 kk = key64[t];
        int idx = (int)(~(unsigned)(kk & 0xFFFFFFFFull));
        g_topS[t] = g_scores[idx];
        const float* row = pred + (long long)idx * 85;
        float x = row[0], y = row[1], w = row[2], h = row[3];
        float hw = __fmul_rn(w, 0.5f), hh = __fmul_rn(h, 0.5f);
        float4 b;
        b.x = __fsub_rn(x, hw); b.y = __fsub_rn(y, hh);
        b.z = __fadd_rn(x, hw); b.w = __fadd_rn(y, hh);
        float c   = g_cls[idx];
        float off = __fmul_rn(c, MAXWH);
        float4 bo;
        bo.x = __fadd_rn(b.x, off); bo.y = __fadd_rn(b.y, off);
        bo.z = __fadd_rn(b.z, off); bo.w = __fadd_rn(b.w, off);
        g_b[t] = b; g_c[t] = c; g_boff[t] = bo;
    }
}

/* -- stage 3: suppression mask -> sparse edges + dense fallback ----------- */
__global__ void mask_kernel() {
    __shared__ float4 jb[64];
    int jblk = blockIdx.x;
    /* lower-triangle words (never read) : skip whole block */
    if (jblk < (int)blockIdx.y * 4) return;
    int tid = threadIdx.x;
    if (tid < 64) jb[tid] = g_boff[jblk * 64 + tid];
    __syncthreads();
    int i = blockIdx.y * 256 + tid;
    float4 a = g_boff[i];
    float areaA = __fmul_rn(__fsub_rn(a.z, a.x), __fsub_rn(a.w, a.y));
    u64 bits = 0;
    int jbase = jblk * 64;
    #pragma unroll 8
    for (int jj = 0; jj < 64; jj++) {
        int j = jbase + jj;
        if (j <= i) continue;                  /* ar > i */
        float4 bb = jb[jj];
        float lx = fmaxf(a.x, bb.x), ly = fmaxf(a.y, bb.y);
        float rx = fminf(a.z, bb.z), ry = fminf(a.w, bb.w);
        float w = fmaxf(__fsub_rn(rx, lx), 0.0f);
        float h = fmaxf(__fsub_rn(ry, ly), 0.0f);
        float inter = __fmul_rn(w, h);
        float areaB = __fmul_rn(__fsub_rn(bb.z, bb.x), __fsub_rn(bb.w, bb.y));
        float denom = __fadd_rn(__fsub_rn(__fadd_rn(areaA, areaB), inter), 1e-7f);
        float iou = __fdiv_rn(inter, denom);
        if (iou > IOU_T) {
            bits |= (1ull << jj);
            int p = atomicAdd(&g_edgeCnt, 1);           /* rare (~60 total) */
            if (p < ECAP)
                g_edges[p] = (((unsigned)i) << 12) | (unsigned)j;
        }
    }
    g_maskM[(long long)i * ROWW + jblk] = bits;
    if (bits) atomicOr(&g_nz[i >> 6], 1u << jblk);
}

/* -- stage 4: block-parallel NMS + finalize (serial part = edge chain) ---- */
__global__ void __launch_bounds__(1024) nms_finalize_kernel(float* __restrict__ out) {
    __shared__ unsigned se[ECAP];              /* sorted edge keys */
    __shared__ u64      sm_alive[ROWW];
    __shared__ u64      sd[64];
    __shared__ unsigned snz[32];
    __shared__ int      wpre[ROWW];
    const unsigned FULL = 0xffffffffu;
    int tid = threadIdx.x;

    int cnt = g_edgeCnt;                       /* uniform broadcast load */

    /* zero det output in parallel */
    float4* o4 = (float4*)out;
    for (int q = tid; q < MAXDET * 6 / 4; q += 1024)
        o4[q] = make_float4(0.f, 0.f, 0.f, 0.f);

    /* alive bits: thread t<32 owns indices [64t, 64t+64) */
    if (tid < 32) {
        u64 alive = 0;
        const float4* ts = (const float4*)g_topS + tid * 16;
        #pragma unroll
        for (int q = 0; q < 16; q++) {
            float4 v = ts[q];
            if (v.x > CONF_T) alive |= 1ull << (4 * q + 0);
            if (v.y > CONF_T) alive |= 1ull << (4 * q + 1);
            if (v.z > CONF_T) alive |= 1ull << (4 * q + 2);
            if (v.w > CONF_T) alive |= 1ull << (4 * q + 3);
        }
        sm_alive[tid] = alive;
    }
    __syncthreads();

    if (cnt <= ECAP) {
        /* ---------- sparse path: warp 0 sorts edges, one thread greedy ---- */
        if (tid < 32) {
            int P = 32;
            while (P < cnt) P <<= 1;
            for (int t = tid; t < P; t += 32)
                se[t] = (t < cnt) ? g_edges[t] : 0xFFFFFFFFu;
            __syncwarp();
            for (int k = 2; k <= P; k <<= 1) {
                for (int j2 = k >> 1; j2; j2 >>= 1) {
                    for (int t = tid; t < P; t += 32) {
                        int l = t ^ j2;
                        if (l > t) {
                            unsigned a = se[t], b = se[l];
                            bool up = ((t & k) == 0);
                            if (up ? (a > b) : (a < b)) { se[t] = b; se[l] = a; }
                        }
                    }
                    __syncwarp();
                }
            }
            if (tid == 0) {
                for (int e = 0; e < cnt; e++) {
                    unsigned k = se[e];
                    int i = k >> 12, j = k & 0xFFF;
                    if ((sm_alive[i >> 6] >> (i & 63)) & 1ull)
                        sm_alive[j >> 6] &= ~(1ull << (j & 63));
                }
            }
        }
    } else {
        /* ---------- dense fallback: warp 0, block-sparse bitmatrix walk --- */
        if (tid < 32) {
            int lane = tid;
            u64 alive = sm_alive[lane];
            snz[lane] = g_nz[lane];
            __syncwarp();
            for (int w = 0; w < ROWW; w++) {
                unsigned nzw = snz[w];
                u64 aw = __shfl_sync(FULL, alive, w);
                if (nzw & (1u << w)) {
                    sd[2 * lane]     = g_maskM[(size_t)(w * 64 + 2 * lane)     * ROWW + w];
                    sd[2 * lane + 1] = g_maskM[(size_t)(w * 64 + 2 * lane + 1) * ROWW + w];
                    __syncwarp();
                    #pragma unroll
                    for (int c = 0; c < 4; c++) {
                        u64 t[16];
                        #pragma unroll
                        for (int k = 0; k < 16; k++) t[k] = sd[c * 16 + k];
                        #pragma unroll
                        for (int k = 0; k < 16; k++) {
                            int b = c * 16 + k;
                            u64 m = (u64)((long long)(aw << (63 - b)) >> 63);
                            aw &= ~(t[k] & m);
                        }
                    }
                    __syncwarp();
                }
                if (lane == w) {
                    alive = aw;
                } else if (lane > w && (nzw & (1u << lane))) {
                    const u64* colp = g_maskM + (size_t)(w * 64) * ROWW + lane;
                    u64 cl[64];
                    #pragma unroll
                    for (int b = 0; b < 64; b++) cl[b] = colp[(size_t)b * ROWW];
                    u64 sup = 0;
                    #pragma unroll
                    for (int b = 0; b < 64; b++) {
                        u64 m = (u64)((long long)(aw << (63 - b)) >> 63);
                        sup |= cl[b] & m;
                    }
                    alive &= ~sup;
                }
            }
            sm_alive[lane] = alive;
        }
    }
    __syncthreads();

    /* exclusive prefix of per-word popcounts (warp 0) */
    if (tid < 32) {
        int c = __popcll(sm_alive[tid]);
        int p = c;
        #pragma unroll
        for (int off = 1; off < 32; off <<= 1) {
            int v = __shfl_up_sync(FULL, p, off);
            if (tid >= off) p += v;
        }
        wpre[tid] = p - c;
    }
    __syncthreads();

    /* parallel survivor emit: one thread per candidate (2 rounds) */
    for (int i = tid; i < KSEL; i += 1024) {
        u64 word = sm_alive[i >> 6];
        if ((word >> (i & 63)) & 1ull) {
            int rank = wpre[i >> 6] + __popcll(word & ((1ull << (i & 63)) - 1ull));
            if (rank < MAXDET) {
                float4 bb = g_b[i];
                float* o = out + rank * 6;
                o[0] = bb.x; o[1] = bb.y; o[2] = bb.z; o[3] = bb.w;
                o[4] = g_topS[i]; o[5] = g_c[i];
            }
        }
    }
}

/* ---------------- stage 5: image BGR/CHW/255, coalesced ------------------ */
__global__ void img_kernel(const int* __restrict__ img, float* __restrict__ out) {
    int r = blockIdx.x * blockDim.x + threadIdx.x;
    if (r >= IMG_PIX) return;
    int b = img[3 * r], g = img[3 * r + 1], rr = img[3 * r + 2];
    out[r]               = __fdiv_rn((float)rr, 255.0f);  /* [::-1] flip */
    out[IMG_PIX + r]     = __fdiv_rn((float)g,  255.0f);
    out[2 * IMG_PIX + r] = __fdiv_rn((float)b,  255.0f);
}

/* ---------------- launch ------------------------------------------------- */
extern "C" void kernel_launch(void* const* d_in, const int* in_sizes, int n_in,
                              void* d_out, int out_size) {
    (void)in_sizes; (void)n_in; (void)out_size;
    const int*   img  = (const int*)d_in[0];
    const float* pred = (const float*)d_in[1];   /* batch 0 only is needed */
    float* out = (float*)d_out;                  /* [det(1000*6) | x(3*640*640)] */

    prep_kernel         <<<(NN + 7) / 8, 256>>>(pred);
    topk_kernel         <<<1, 1024>>>(pred);
    mask_kernel         <<<dim3(32, 8), 256>>>();
    nms_finalize_kernel <<<1, 1024>>>(out);
    img_kernel          <<<(IMG_PIX + 255) / 256, 256>>>(img, out + MAXDET * 6);
}

// round 13
// speedup vs baseline: 4.0735x; 1.1223x over previous
#include <cuda_runtime.h>

#define NN      25200
#define KSEL    2048
#define NCLS    80
#define CONF_T  0.4f
#define IOU_T   0.45f
#define MAXDET  1000
#define MAXWH   7680.0f
#define ROWW    32          /* 2048/64 uint64 words per mask row */
#define IMG_PIX (640*640)
#define ECAP    2048        /* sparse edge-list capacity */
#define MBLK    (32*8)      /* mask grid blocks */

typedef unsigned long long u64;

/* ---------------- scratch (device globals; no allocation) ---------------- */
__device__ float              g_scores[NN];
__device__ float              g_cls[NN];
__device__ unsigned           g_key32[NN];
__device__ __align__(16) float g_topS[KSEL];
__device__ float4             g_b[KSEL];      /* unshifted xyxy of sorted cands */
__device__ float              g_c[KSEL];      /* class as float */
__device__ float4             g_boff[KSEL];   /* class-offset boxes for IoU */
__device__ u64                g_maskM[KSEL * ROWW]; /* dense fallback matrix */
__device__ unsigned           g_nz[ROWW];     /* block-nonzero bitmap (fallback) */
__device__ int                g_edgeCnt;
__device__ unsigned           g_edges[ECAP];  /* (i<<12)|j suppression pairs */
__device__ unsigned           g_alive32[64];  /* conf>thr bitmap (topk ballots) */
__device__ unsigned           g_doneCtr;      /* mask completion counter */

/* ------- stage 1: per-anchor conf/cls/key + fused image normalize -------- */
__global__ void prep_img_kernel(const float* __restrict__ pred,
                                const int* __restrict__ img,
                                float* __restrict__ outx) {
    int gid = blockIdx.x * blockDim.x + threadIdx.x;
    if (blockIdx.x == 0) {
        if (threadIdx.x < ROWW) g_nz[threadIdx.x] = 0;
        if (threadIdx.x == 0)   g_edgeCnt = 0;
    }
    /* image part: first 1600 blocks cover all pixels */
    if (gid < IMG_PIX) {
        int b = img[3 * gid], g = img[3 * gid + 1], rr = img[3 * gid + 2];
        outx[gid]               = __fdiv_rn((float)rr, 255.0f);  /* [::-1] */
        outx[IMG_PIX + gid]     = __fdiv_rn((float)g,  255.0f);
        outx[2 * IMG_PIX + gid] = __fdiv_rn((float)b,  255.0f);
    }
    /* prep part: one warp per anchor */
    int anchor = gid >> 5;
    int lane   = threadIdx.x & 31;
    if (anchor >= NN) return;
    const float* row = pred + (long long)anchor * 85;
    float obj = row[4];
    float best = -1.0f;
    int   bc   = 0;
    for (int j = lane; j < NCLS; j += 32) {
        float v = __fmul_rn(row[5 + j], obj);
        if (v > best) { best = v; bc = j; }       /* strict > -> first max */
    }
    /* warp argmax, ties -> lowest class index (jnp.argmax semantics) */
    for (int off = 16; off; off >>= 1) {
        float ov = __shfl_down_sync(0xffffffffu, best, off);
        int   oc = __shfl_down_sync(0xffffffffu, bc, off);
        if (ov > best || (ov == best && oc < bc)) { best = ov; bc = oc; }
    }
    if (lane == 0) {
        float s = (best > CONF_T) ? best : -1.0f;
        g_scores[anchor] = s;
        g_cls[anchor]    = (float)bc;
        unsigned u = __float_as_uint(s);
        g_key32[anchor] = (u >> 31) ? ~u : (u | 0x80000000u);  /* order-preserving */
    }
}

/* -------- stage 2: radix-select + bitonic top-2048 + fused gather -------- */
__global__ void topk_kernel(const float* __restrict__ pred) {
    __shared__ int bins[256];
    __shared__ int s_sel, s_acc, s_cnt;
    __shared__ u64 key64[KSEL];
    const unsigned FULL = 0xffffffffu;
    int tid = threadIdx.x;

    /* 4x8-bit radix select: find T = 2048th-largest key.
       match_any dedups hot bins -> 1 atomic per distinct bin per warp. */
    unsigned prefixv = 0;
    int need = KSEL;
    for (int shift = 24; shift >= 0; shift -= 8) {
        for (int b = tid; b < 256; b += blockDim.x) bins[b] = 0;
        __syncthreads();
        unsigned hmask = (shift == 24) ? 0u : (0xFFFFFFFFu << (shift + 8));
        for (int base = 0; base < NN; base += blockDim.x) {
            int i = base + tid;
            bool in = (i < NN);
            unsigned k = in ? g_key32[i] : 0u;
            bool act = in && ((k & hmask) == prefixv);
            unsigned bin = (k >> shift) & 255u;
            unsigned active = __ballot_sync(FULL, act);
            if (act) {
                unsigned grp = __match_any_sync(active, bin);
                if ((tid & 31) == (__ffs(grp) - 1))
                    atomicAdd(&bins[bin], __popc(grp));
            }
        }
        __syncthreads();
        if (tid == 0) {
            int acc = 0, v = 0;
            for (int b = 255; b >= 0; b--) {
                if (acc + bins[b] >= need) { v = b; break; }
                acc += bins[b];
            }
            s_sel = v; s_acc = acc;
        }
        __syncthreads();
        prefixv |= ((unsigned)s_sel) << shift;
        need -= s_acc;
        __syncthreads();
    }

    /* gather all keys >= T (>= 2048 exist), cap at 2048 */
    if (tid == 0) s_cnt = 0;
    __syncthreads();
    for (int i = tid; i < NN; i += blockDim.x) {
        unsigned k = g_key32[i];
        if (k >= prefixv) {
            int p = atomicAdd(&s_cnt, 1);
            if (p < KSEL)
                key64[p] = (((u64)k) << 32) | (unsigned)(~(unsigned)i);
        }
    }
    __syncthreads();

    /* bitonic sort 2048 keys descending; ~index low bits => lowest index
       wins ties; gather order becomes irrelevant (deterministic) */
    for (unsigned k = 2; k <= KSEL; k <<= 1) {
        for (unsigned j = k >> 1; j; j >>= 1) {
            for (unsigned t = tid; t < KSEL; t += blockDim.x) {
                unsigned l = t ^ j;
                if (l > t) {
                    u64 a = key64[t], b = key64[l];
                    bool descBlk = ((t & k) == 0);
                    bool sw = descBlk ? (a < b) : (a > b);
                    if (sw) { key64[t] = b; key64[l] = a; }
                }
            }
            __syncthreads();
        }
    }

    /* fused gather: boxes, class offsets, scores + alive ballots */
    for (int t = tid; t < KSEL; t += blockDim.x) {
        u64 kk = key64[t];
        int idx = (int)(~(unsigned)(kk & 0xFFFFFFFFull));
        float s = g_scores[idx];
        g_topS[t] = s;
        unsigned bal = __ballot_sync(FULL, s > CONF_T);
        if ((tid & 31) == 0) g_alive32[t >> 5] = bal;
        const float* row = pred + (long long)idx * 85;
        float x = row[0], y = row[1], w = row[2], h = row[3];
        float hw = __fmul_rn(w, 0.5f), hh = __fmul_rn(h, 0.5f);
        float4 b;
        b.x = __fsub_rn(x, hw); b.y = __fsub_rn(y, hh);
        b.z = __fadd_rn(x, hw); b.w = __fadd_rn(y, hh);
        float c   = g_cls[idx];
        float off = __fmul_rn(c, MAXWH);
        float4 bo;
        bo.x = __fadd_rn(b.x, off); bo.y = __fadd_rn(b.y, off);
        bo.z = __fadd_rn(b.z, off); bo.w = __fadd_rn(b.w, off);
        g_b[t] = b; g_c[t] = c; g_boff[t] = bo;
    }
}

/* -- stage 3: suppression edges (div-free fast path) + last-block NMS ----- */
__global__ void __launch_bounds__(256) mask_nms_kernel(float* __restrict__ out) {
    __shared__ float4   jb[64];
    __shared__ float    jA[64];
    __shared__ unsigned se[ECAP];
    __shared__ u64      sm_alive[ROWW];
    __shared__ u64      sd[64];
    __shared__ unsigned snz[32];
    __shared__ int      wpre[ROWW];
    __shared__ bool     s_last;
    const unsigned FULL = 0xffffffffu;
    int tid = threadIdx.x;
    int jblk = blockIdx.x;
    bool skip = (jblk < (int)blockIdx.y * 4);   /* lower-triangle words */

    if (!skip) {
        if (tid < 64) {
            float4 bb = g_boff[jblk * 64 + tid];
            jb[tid] = bb;
            jA[tid] = __fmul_rn(__fsub_rn(bb.z, bb.x), __fsub_rn(bb.w, bb.y));
        }
        __syncthreads();
        int i = blockIdx.y * 256 + tid;
        float4 a = g_boff[i];
        float areaA = __fmul_rn(__fsub_rn(a.z, a.x), __fsub_rn(a.w, a.y));
        u64 bits = 0;
        int jbase = jblk * 64;
        #pragma unroll 8
        for (int jj = 0; jj < 64; jj++) {
            int j = jbase + jj;
            if (j <= i) continue;              /* ar > i */
            float4 bb = jb[jj];
            float lx = fmaxf(a.x, bb.x), ly = fmaxf(a.y, bb.y);
            float rx = fminf(a.z, bb.z), ry = fminf(a.w, bb.w);
            float w = fmaxf(__fsub_rn(rx, lx), 0.0f);
            float h = fmaxf(__fsub_rn(ry, ly), 0.0f);
            float inter = __fmul_rn(w, h);
            /* inter==0 -> iou==0 -> never suppresses; exact div only when >0 */
            if (inter > 0.0f) {
                float denom = __fadd_rn(
                    __fsub_rn(__fadd_rn(areaA, jA[jj]), inter), 1e-7f);
                float iou = __fdiv_rn(inter, denom);
                if (iou > IOU_T) {
                    bits |= (1ull << jj);
                    int p = atomicAdd(&g_edgeCnt, 1);   /* rare (~60 total) */
                    if (p < ECAP)
                        g_edges[p] = (((unsigned)i) << 12) | (unsigned)j;
                }
            }
        }
        g_maskM[(long long)i * ROWW + jblk] = bits;
        if (bits) atomicOr(&g_nz[i >> 6], 1u << jblk);
    }

    /* ---- completion: last finishing block runs NMS + finalize ---- */
    __threadfence();
    if (tid == 0)
        s_last = (atomicAdd(&g_doneCtr, 1) == (unsigned)(MBLK - 1));
    __syncthreads();
    if (!s_last) return;
    __threadfence();
    if (tid == 0) g_doneCtr = 0;               /* reset for graph replay */

    int cnt = g_edgeCnt;

    /* zero det output */
    float4* o4 = (float4*)out;
    for (int q = tid; q < MAXDET * 6 / 4; q += 256)
        o4[q] = make_float4(0.f, 0.f, 0.f, 0.f);

    if (tid < 32)
        sm_alive[tid] = (u64)g_alive32[2 * tid]
                      | ((u64)g_alive32[2 * tid + 1] << 32);
    __syncthreads();

    if (cnt <= ECAP) {
        /* sparse path: block-sorts edge list, one thread runs exact greedy */
        int P = 32;
        while (P < cnt) P <<= 1;
        for (int t = tid; t < P; t += 256)
            se[t] = (t < cnt) ? g_edges[t] : 0xFFFFFFFFu;
        __syncthreads();
        for (int k = 2; k <= P; k <<= 1) {
            for (int j2 = k >> 1; j2; j2 >>= 1) {
                for (int t = tid; t < P; t += 256) {
                    int l = t ^ j2;
                    if (l > t) {
                        unsigned a = se[t], b = se[l];
                        bool up = ((t & k) == 0);
                        if (up ? (a > b) : (a < b)) { se[t] = b; se[l] = a; }
                    }
                }
                __syncthreads();
            }
        }
        if (tid == 0) {
            for (int e = 0; e < cnt; e++) {
                unsigned k = se[e];
                int i = k >> 12, j = k & 0xFFF;
                if ((sm_alive[i >> 6] >> (i & 63)) & 1ull)
                    sm_alive[j >> 6] &= ~(1ull << (j & 63));
            }
        }
        __syncthreads();
    } else {
        /* dense fallback: warp 0 block-sparse bitmatrix walk */
        if (tid < 32) {
            int lane = tid;
            u64 alive = sm_alive[lane];
            snz[lane] = g_nz[lane];
            __syncwarp();
            for (int w = 0; w < ROWW; w++) {
                unsigned nzw = snz[w];
                u64 aw = __shfl_sync(FULL, alive, w);
                if (nzw & (1u << w)) {
                    sd[2 * lane]     = g_maskM[(size_t)(w * 64 + 2 * lane)     * ROWW + w];
                    sd[2 * lane + 1] = g_maskM[(size_t)(w * 64 + 2 * lane + 1) * ROWW + w];
                    __syncwarp();
                    #pragma unroll
                    for (int c = 0; c < 4; c++) {
                        u64 t[16];
                        #pragma unroll
                        for (int k = 0; k < 16; k++) t[k] = sd[c * 16 + k];
                        #pragma unroll
                        for (int k = 0; k < 16; k++) {
                            int b = c * 16 + k;
                            u64 m = (u64)((long long)(aw << (63 - b)) >> 63);
                            aw &= ~(t[k] & m);
                        }
                    }
                    __syncwarp();
                }
                if (lane == w) {
                    alive = aw;
                } else if (lane > w && (nzw & (1u << lane))) {
                    const u64* colp = g_maskM + (size_t)(w * 64) * ROWW + lane;
                    u64 cl[64];
                    #pragma unroll
                    for (int b = 0; b < 64; b++) cl[b] = colp[(size_t)b * ROWW];
                    u64 sup = 0;
                    #pragma unroll
                    for (int b = 0; b < 64; b++) {
                        u64 m = (u64)((long long)(aw << (63 - b)) >> 63);
                        sup |= cl[b] & m;
                    }
                    alive &= ~sup;
                }
            }
            sm_alive[lane] = alive;
        }
        __syncthreads();
    }

    /* exclusive prefix of per-word popcounts (warp 0) */
    if (tid < 32) {
        int c = __popcll(sm_alive[tid]);
        int p = c;
        #pragma unroll
        for (int off = 1; off < 32; off <<= 1) {
            int v = __shfl_up_sync(FULL, p, off);
            if (tid >= off) p += v;
        }
        wpre[tid] = p - c;
    }
    __syncthreads();

    /* parallel survivor emit */
    for (int i = tid; i < KSEL; i += 256) {
        u64 word = sm_alive[i >> 6];
        if ((word >> (i & 63)) & 1ull) {
            int rank = wpre[i >> 6] + __popcll(word & ((1ull << (i & 63)) - 1ull));
            if (rank < MAXDET) {
                float4 bb = g_b[i];
                float* o = out + rank * 6;
                o[0] = bb.x; o[1] = bb.y; o[2] = bb.z; o[3] = bb.w;
                o[4] = g_topS[i]; o[5] = g_c[i];
            }
        }
    }
}

/* ---------------- launch ------------------------------------------------- */
extern "C" void kernel_launch(void* const* d_in, const int* in_sizes, int n_in,
                              void* d_out, int out_size) {
    (void)in_sizes; (void)n_in; (void)out_size;
    const int*   img  = (const int*)d_in[0];
    const float* pred = (const float*)d_in[1];   /* batch 0 only is needed */
    float* out = (float*)d_out;                  /* [det(1000*6) | x(3*640*640)] */

    prep_img_kernel <<<(NN + 7) / 8, 256>>>(pred, img, out + MAXDET * 6);
    topk_kernel     <<<1, 1024>>>(pred);
    mask_nms_kernel <<<dim3(32, 8), 256>>>(out);
}

// round 15
// speedup vs baseline: 4.1733x; 1.0245x over previous
#include <cuda_runtime.h>

#define NN      25200
#define KSEL    2048
#define NCLS    80
#define CONF_T  0.4f
#define IOU_T   0.45f
#define MAXDET  1000
#define MAXWH   7680.0f
#define ROWW    32          /* 2048/64 uint64 words per mask row */
#define IMG_PIX (640*640)
#define ECAP    2048        /* sparse edge-list capacity */
#define MBLK    (32*8)      /* mask grid blocks */
#define PBLK    788         /* prep blocks: ceil(25200/32) warps-per-anchor */

typedef unsigned long long u64;

/* ---------------- scratch (device globals; no allocation) ---------------- */
__device__ float              g_scores[NN];
__device__ float              g_cls[NN];
__device__ unsigned           g_key32[NN];
__device__ __align__(16) float g_topS[KSEL];
__device__ float4             g_b[KSEL];      /* unshifted xyxy of sorted cands */
__device__ float              g_c[KSEL];      /* class as float */
__device__ float4             g_boff[KSEL];   /* class-offset boxes for IoU */
__device__ u64                g_maskM[KSEL * ROWW]; /* dense fallback matrix */
__device__ unsigned           g_nz[ROWW];     /* block-nonzero bitmap (fallback) */
__device__ int                g_edgeCnt;
__device__ unsigned           g_edges[ECAP];  /* (i<<12)|j suppression pairs */
__device__ unsigned           g_alive32[64];  /* conf>thr bitmap (topk ballots) */
__device__ unsigned           g_doneCtr;      /* mask completion counter */
__device__ unsigned           g_prepCtr;      /* prep completion counter */

/* ---- stage 1+2: prep + img, last-done block runs topk in-kernel --------- */
__global__ void __launch_bounds__(1024)
prep_topk_kernel(const float* __restrict__ pred,
                 const int* __restrict__ img,
                 float* __restrict__ outx) {
    const unsigned FULL = 0xffffffffu;
    int tid = threadIdx.x;
    int gid = blockIdx.x * blockDim.x + tid;

    if (blockIdx.x == 0) {
        if (tid < ROWW) g_nz[tid] = 0;
        if (tid == 0)   g_edgeCnt = 0;
    }

    /* image normalize: first 400 blocks cover all pixels */
    if (gid < IMG_PIX) {
        int b = img[3 * gid], g = img[3 * gid + 1], rr = img[3 * gid + 2];
        outx[gid]               = __fdiv_rn((float)rr, 255.0f);  /* [::-1] */
        outx[IMG_PIX + gid]     = __fdiv_rn((float)g,  255.0f);
        outx[2 * IMG_PIX + gid] = __fdiv_rn((float)b,  255.0f);
    }

    /* per-anchor conf/cls/key: one warp per anchor, loop peeled */
    int anchor = gid >> 5;
    int lane   = tid & 31;
    if (anchor < NN) {
        const float* row = pred + (long long)anchor * 85;
        float obj = row[4];                    /* same-addr broadcast load */
        /* candidates at class indices lane, lane+32, lane+64 (ascending) */
        float best = __fmul_rn(row[5 + lane], obj);
        int   bc   = lane;
        float v1   = __fmul_rn(row[37 + lane], obj);
        if (v1 > best) { best = v1; bc = lane + 32; }
        if (lane < 16) {
            float v2 = __fmul_rn(row[69 + lane], obj);
            if (v2 > best) { best = v2; bc = lane + 64; }
        }
        /* warp argmax, ties -> lowest class index */
        #pragma unroll
        for (int off = 16; off; off >>= 1) {
            float ov = __shfl_down_sync(FULL, best, off);
            int   oc = __shfl_down_sync(FULL, bc, off);
            if (ov > best || (ov == best && oc < bc)) { best = ov; bc = oc; }
        }
        if (lane == 0) {
            float s = (best > CONF_T) ? best : -1.0f;
            g_scores[anchor] = s;
            g_cls[anchor]    = (float)bc;
            unsigned u = __float_as_uint(s);
            g_key32[anchor] = (u >> 31) ? ~u : (u | 0x80000000u);
        }
    }

    /* ---- completion: last finishing block runs topk ---- */
    __shared__ bool s_last;
    __threadfence();
    __syncthreads();
    if (tid == 0)
        s_last = (atomicAdd(&g_prepCtr, 1) == (unsigned)(PBLK - 1));
    __syncthreads();
    if (!s_last) return;
    __threadfence();
    if (tid == 0) g_prepCtr = 0;               /* reset for graph replay */

    /* ================= topk phase (single block, 1024 thr) ================ */
    __shared__ int bins[256];
    __shared__ int s_sel, s_acc, s_cnt;
    __shared__ u64 key64[KSEL];

    /* 4x8-bit radix select: find T = 2048th-largest key.
       match_any dedups hot bins -> 1 atomic per distinct bin per warp. */
    unsigned prefixv = 0;
    int need = KSEL;
    for (int shift = 24; shift >= 0; shift -= 8) {
        for (int b = tid; b < 256; b += 1024) bins[b] = 0;
        __syncthreads();
        unsigned hmask = (shift == 24) ? 0u : (0xFFFFFFFFu << (shift + 8));
        for (int base = 0; base < NN; base += 1024) {
            int i = base + tid;
            bool in = (i < NN);
            unsigned k = in ? g_key32[i] : 0u;
            bool act = in && ((k & hmask) == prefixv);
            unsigned bin = (k >> shift) & 255u;
            unsigned active = __ballot_sync(FULL, act);
            if (act) {
                unsigned grp = __match_any_sync(active, bin);
                if ((tid & 31) == (__ffs(grp) - 1))
                    atomicAdd(&bins[bin], __popc(grp));
            }
        }
        __syncthreads();
        if (tid == 0) {
            int acc = 0, v = 0;
            for (int b = 255; b >= 0; b--) {
                if (acc + bins[b] >= need) { v = b; break; }
                acc += bins[b];
            }
            s_sel = v; s_acc = acc;
        }
        __syncthreads();
        prefixv |= ((unsigned)s_sel) << shift;
        need -= s_acc;
        __syncthreads();
    }

    /* gather all keys >= T (>= 2048 exist), cap at 2048 */
    if (tid == 0) s_cnt = 0;
    __syncthreads();
    for (int i = tid; i < NN; i += 1024) {
        unsigned k = g_key32[i];
        if (k >= prefixv) {
            int p = atomicAdd(&s_cnt, 1);
            if (p < KSEL)
                key64[p] = (((u64)k) << 32) | (unsigned)(~(unsigned)i);
        }
    }
    __syncthreads();

    /* bitonic sort 2048 keys descending; ~index low bits => lowest index
       wins ties; gather order irrelevant (deterministic) */
    for (unsigned k = 2; k <= KSEL; k <<= 1) {
        for (unsigned j = k >> 1; j; j >>= 1) {
            for (unsigned t = tid; t < KSEL; t += 1024) {
                unsigned l = t ^ j;
                if (l > t) {
                    u64 a = key64[t], b = key64[l];
                    bool descBlk = ((t & k) == 0);
                    bool sw = descBlk ? (a < b) : (a > b);
                    if (sw) { key64[t] = b; key64[l] = a; }
                }
            }
            __syncthreads();
        }
    }

    /* fused gather: boxes, class offsets, scores + alive ballots */
    for (int t = tid; t < KSEL; t += 1024) {
        u64 kk = key64[t];
        int idx = (int)(~(unsigned)(kk & 0xFFFFFFFFull));
        float s = g_scores[idx];
        g_topS[t] = s;
        unsigned bal = __ballot_sync(FULL, s > CONF_T);
        if ((tid & 31) == 0) g_alive32[t >> 5] = bal;
        const float* row = pred + (long long)idx * 85;
        float x = row[0], y = row[1], w = row[2], h = row[3];
        float hw = __fmul_rn(w, 0.5f), hh = __fmul_rn(h, 0.5f);
        float4 b;
        b.x = __fsub_rn(x, hw); b.y = __fsub_rn(y, hh);
        b.z = __fadd_rn(x, hw); b.w = __fadd_rn(y, hh);
        float c   = g_cls[idx];
        float off = __fmul_rn(c, MAXWH);
        float4 bo;
        bo.x = __fadd_rn(b.x, off); bo.y = __fadd_rn(b.y, off);
        bo.z = __fadd_rn(b.z, off); bo.w = __fadd_rn(b.w, off);
        g_b[t] = b; g_c[t] = c; g_boff[t] = bo;
    }
}

/* -- stage 3: suppression edges (div-free fast path) + last-block NMS ----- */
__global__ void __launch_bounds__(256) mask_nms_kernel(float* __restrict__ out) {
    __shared__ float4   jb[64];
    __shared__ float    jA[64];
    __shared__ unsigned se[ECAP];
    __shared__ u64      sm_alive[ROWW];
    __shared__ u64      sd[64];
    __shared__ unsigned snz[32];
    __shared__ int      wpre[ROWW];
    __shared__ bool     s_last;
    const unsigned FULL = 0xffffffffu;
    int tid = threadIdx.x;
    int jblk = blockIdx.x;
    bool skip = (jblk < (int)blockIdx.y * 4);   /* lower-triangle words */

    if (!skip) {
        if (tid < 64) {
            float4 bb = g_boff[jblk * 64 + tid];
            jb[tid] = bb;
            jA[tid] = __fmul_rn(__fsub_rn(bb.z, bb.x), __fsub_rn(bb.w, bb.y));
        }
        __syncthreads();
        int i = blockIdx.y * 256 + tid;
        float4 a = g_boff[i];
        float areaA = __fmul_rn(__fsub_rn(a.z, a.x), __fsub_rn(a.w, a.y));
        u64 bits = 0;
        int jbase = jblk * 64;
        #pragma unroll 8
        for (int jj = 0; jj < 64; jj++) {
            int j = jbase + jj;
            if (j <= i) continue;              /* ar > i */
            float4 bb = jb[jj];
            float lx = fmaxf(a.x, bb.x), ly = fmaxf(a.y, bb.y);
            float rx = fminf(a.z, bb.z), ry = fminf(a.w, bb.w);
            float w = fmaxf(__fsub_rn(rx, lx), 0.0f);
            float h = fmaxf(__fsub_rn(ry, ly), 0.0f);
            float inter = __fmul_rn(w, h);
            /* inter==0 -> iou==0 -> never suppresses; exact div only when >0 */
            if (inter > 0.0f) {
                float denom = __fadd_rn(
                    __fsub_rn(__fadd_rn(areaA, jA[jj]), inter), 1e-7f);
                float iou = __fdiv_rn(inter, denom);
                if (iou > IOU_T) {
                    bits |= (1ull << jj);
                    int p = atomicAdd(&g_edgeCnt, 1);   /* rare (~60 total) */
                    if (p < ECAP)
                        g_edges[p] = (((unsigned)i) << 12) | (unsigned)j;
                }
            }
        }
        g_maskM[(long long)i * ROWW + jblk] = bits;
        if (bits) atomicOr(&g_nz[i >> 6], 1u << jblk);
    }

    /* ---- completion: last finishing block runs NMS + finalize ---- */
    __threadfence();
    if (tid == 0)
        s_last = (atomicAdd(&g_doneCtr, 1) == (unsigned)(MBLK - 1));
    __syncthreads();
    if (!s_last) return;
    __threadfence();
    if (tid == 0) g_doneCtr = 0;               /* reset for graph replay */

    int cnt = g_edgeCnt;

    /* zero det output */
    float4* o4 = (float4*)out;
    for (int q = tid; q < MAXDET * 6 / 4; q += 256)
        o4[q] = make_float4(0.f, 0.f, 0.f, 0.f);

    if (tid < 32)
        sm_alive[tid] = (u64)g_alive32[2 * tid]
                      | ((u64)g_alive32[2 * tid + 1] << 32);
    __syncthreads();

    if (cnt <= ECAP) {
        /* sparse path: block-sorts edge list, one thread runs exact greedy */
        int P = 32;
        while (P < cnt) P <<= 1;
        for (int t = tid; t < P; t += 256)
            se[t] = (t < cnt) ? g_edges[t] : 0xFFFFFFFFu;
        __syncthreads();
        for (int k = 2; k <= P; k <<= 1) {
            for (int j2 = k >> 1; j2; j2 >>= 1) {
                for (int t = tid; t < P; t += 256) {
                    int l = t ^ j2;
                    if (l > t) {
                        unsigned a = se[t], b = se[l];
                        bool up = ((t & k) == 0);
                        if (up ? (a > b) : (a < b)) { se[t] = b; se[l] = a; }
                    }
                }
                __syncthreads();
            }
        }
        if (tid == 0) {
            for (int e = 0; e < cnt; e++) {
                unsigned k = se[e];
                int i = k >> 12, j = k & 0xFFF;
                if ((sm_alive[i >> 6] >> (i & 63)) & 1ull)
                    sm_alive[j >> 6] &= ~(1ull << (j & 63));
            }
        }
        __syncthreads();
    } else {
        /* dense fallback: warp 0 block-sparse bitmatrix walk */
        if (tid < 32) {
            int lane = tid;
            u64 alive = sm_alive[lane];
            snz[lane] = g_nz[lane];
            __syncwarp();
            for (int w = 0; w < ROWW; w++) {
                unsigned nzw = snz[w];
                u64 aw = __shfl_sync(FULL, alive, w);
                if (nzw & (1u << w)) {
                    sd[2 * lane]     = g_maskM[(size_t)(w * 64 + 2 * lane)     * ROWW + w];
                    sd[2 * lane + 1] = g_maskM[(size_t)(w * 64 + 2 * lane + 1) * ROWW + w];
                    __syncwarp();
                    #pragma unroll
                    for (int c = 0; c < 4; c++) {
                        u64 t[16];
                        #pragma unroll
                        for (int k = 0; k < 16; k++) t[k] = sd[c * 16 + k];
                        #pragma unroll
                        for (int k = 0; k < 16; k++) {
                            int b = c * 16 + k;
                            u64 m = (u64)((long long)(aw << (63 - b)) >> 63);
                            aw &= ~(t[k] & m);
                        }
                    }
                    __syncwarp();
                }
                if (lane == w) {
                    alive = aw;
                } else if (lane > w && (nzw & (1u << lane))) {
                    const u64* colp = g_maskM + (size_t)(w * 64) * ROWW + lane;
                    u64 cl[64];
                    #pragma unroll
                    for (int b = 0; b < 64; b++) cl[b] = colp[(size_t)b * ROWW];
                    u64 sup = 0;
                    #pragma unroll
                    for (int b = 0; b < 64; b++) {
                        u64 m = (u64)((long long)(aw << (63 - b)) >> 63);
                        sup |= cl[b] & m;
                    }
                    alive &= ~sup;
                }
            }
            sm_alive[lane] = alive;
        }
        __syncthreads();
    }

    /* exclusive prefix of per-word popcounts (warp 0) */
    if (tid < 32) {
        int c = __popcll(sm_alive[tid]);
        int p = c;
        #pragma unroll
        for (int off = 1; off < 32; off <<= 1) {
            int v = __shfl_up_sync(FULL, p, off);
            if (tid >= off) p += v;
        }
        wpre[tid] = p - c;
    }
    __syncthreads();

    /* parallel survivor emit */
    for (int i = tid; i < KSEL; i += 256) {
        u64 word = sm_alive[i >> 6];
        if ((word >> (i & 63)) & 1ull) {
            int rank = wpre[i >> 6] + __popcll(word & ((1ull << (i & 63)) - 1ull));
            if (rank < MAXDET) {
                float4 bb = g_b[i];
                float* o = out + rank * 6;
                o[0] = bb.x; o[1] = bb.y; o[2] = bb.z; o[3] = bb.w;
                o[4] = g_topS[i]; o[5] = g_c[i];
            }
        }
    }
}

/* ---------------- launch ------------------------------------------------- */
extern "C" void kernel_launch(void* const* d_in, const int* in_sizes, int n_in,
                              void* d_out, int out_size) {
    (void)in_sizes; (void)n_in; (void)out_size;
    const int*   img  = (const int*)d_in[0];
    const float* pred = (const float*)d_in[1];   /* batch 0 only is needed */
    float* out = (float*)d_out;                  /* [det(1000*6) | x(3*640*640)] */

    prep_topk_kernel <<<PBLK, 1024>>>(pred, img, out + MAXDET * 6);
    mask_nms_kernel  <<<dim3(32, 8), 256>>>(out);
}